// round 1
// baseline (speedup 1.0000x reference)
#include <cuda_runtime.h>

#define BB 64
#define SS 512
#define EE 128
#define TT 10
#define ROWS (BB*SS)

// scratch (static device globals: allocation-free)
__device__ float g_pre[ROWS * 16];  // [row][gate*4+w] x-part preactivation + bias + theta
__device__ float g_h[ROWS * 4];     // hidden states per (b,s)

// ---------------------------------------------------------------------------
// Kernel A: fused embedding gather + GEMM for the x-dependent part of all
// 4 gates' pre-activations. One thread per (row, gate-wire) output.
// ---------------------------------------------------------------------------
__global__ void pre_kernel(const int* __restrict__ x, const float* __restrict__ emb,
                           const float* __restrict__ Wf, const float* __restrict__ bf, const float* __restrict__ thf,
                           const float* __restrict__ Wi, const float* __restrict__ bi, const float* __restrict__ thi,
                           const float* __restrict__ Wu, const float* __restrict__ bu, const float* __restrict__ thu,
                           const float* __restrict__ Wo, const float* __restrict__ bo, const float* __restrict__ tho)
{
    __shared__ float sW[128 * 16];  // sW[k*16 + g*4 + w]
    __shared__ float sC[16];        // bias + theta

    int tid = threadIdx.x;
    for (int idx = tid; idx < 128 * 16; idx += blockDim.x) {
        int k = idx >> 4;
        int g = (idx >> 2) & 3;
        int w = idx & 3;
        const float* Wg = (g == 0) ? Wf : (g == 1) ? Wi : (g == 2) ? Wu : Wo;
        sW[idx] = Wg[k * 4 + w];
    }
    if (tid < 16) {
        int g = tid >> 2, w = tid & 3;
        const float* bg  = (g == 0) ? bf  : (g == 1) ? bi  : (g == 2) ? bu  : bo;
        const float* thg = (g == 0) ? thf : (g == 1) ? thi : (g == 2) ? thu : tho;
        sC[tid] = bg[w] + thg[w];
    }
    __syncthreads();

    int gt  = blockIdx.x * blockDim.x + tid;  // [0, ROWS*16)
    int gw  = gt & 15;
    int row = gt >> 4;
    const float4* e4 = (const float4*)(emb + (size_t)x[row] * EE);

    float a0 = 0.f, a1 = 0.f, a2 = 0.f, a3 = 0.f;
    #pragma unroll
    for (int k4 = 0; k4 < 32; k4++) {
        float4 e = e4[k4];
        int k = k4 * 4;
        a0 = fmaf(e.x, sW[(k + 0) * 16 + gw], a0);
        a1 = fmaf(e.y, sW[(k + 1) * 16 + gw], a1);
        a2 = fmaf(e.z, sW[(k + 2) * 16 + gw], a2);
        a3 = fmaf(e.w, sW[(k + 3) * 16 + gw], a3);
    }
    g_pre[gt] = (a0 + a1) + (a2 + a3) + sC[gw];
}

// ---------------------------------------------------------------------------
// Kernel B: serial LSTM recurrence (hidden = 4). One thread per batch element.
// QLayer collapsed analytically:
//   z_w = cos(a_w);  out = {z1 z2 z3, z0 z1, z0 z1 z2, z0 z1 z2 z3}
// ---------------------------------------------------------------------------
__device__ __forceinline__ float sigmoidf_fast(float v) {
    float e = __expf(-v);
    return __fdividef(1.0f, 1.0f + e);
}
__device__ __forceinline__ float tanhf_fast(float v) {
    float e = __expf(2.0f * v);
    return 1.0f - __fdividef(2.0f, e + 1.0f);
}

__global__ void __launch_bounds__(32, 1) rec_kernel(const float* __restrict__ Wf,
                                                    const float* __restrict__ Wi,
                                                    const float* __restrict__ Wu,
                                                    const float* __restrict__ Wo)
{
    int b = blockIdx.x * blockDim.x + threadIdx.x;
    if (b >= BB) return;

    // hidden-to-gate weights: rows 128..131 of each W
    float Wh[4][4][4];  // [gate][h][w]
    const float* Ws[4] = {Wf, Wi, Wu, Wo};
    #pragma unroll
    for (int g = 0; g < 4; g++)
        #pragma unroll
        for (int h = 0; h < 4; h++)
            #pragma unroll
            for (int w = 0; w < 4; w++)
                Wh[g][h][w] = Ws[g][(128 + h) * 4 + w];

    float hx[4] = {0.f, 0.f, 0.f, 0.f};
    float cx[4] = {0.f, 0.f, 0.f, 0.f};

    const float4* pre4 = (const float4*)g_pre + (size_t)b * SS * 4;
    float4* hout = (float4*)g_h + (size_t)b * SS;

    for (int s = 0; s < SS; s++) {
        float4 pg0 = pre4[s * 4 + 0];
        float4 pg1 = pre4[s * 4 + 1];
        float4 pg2 = pre4[s * 4 + 2];
        float4 pg3 = pre4[s * 4 + 3];
        float p[4][4] = {{pg0.x, pg0.y, pg0.z, pg0.w},
                         {pg1.x, pg1.y, pg1.z, pg1.w},
                         {pg2.x, pg2.y, pg2.z, pg2.w},
                         {pg3.x, pg3.y, pg3.z, pg3.w}};
        float q[4][4];
        #pragma unroll
        for (int g = 0; g < 4; g++) {
            float z[4];
            #pragma unroll
            for (int w = 0; w < 4; w++) {
                float a = p[g][w];
                a = fmaf(hx[0], Wh[g][0][w], a);
                a = fmaf(hx[1], Wh[g][1][w], a);
                a = fmaf(hx[2], Wh[g][2][w], a);
                a = fmaf(hx[3], Wh[g][3][w], a);
                z[w] = __cosf(a);
            }
            float z01 = z[0] * z[1];
            float z12 = z[1] * z[2];
            q[g][0] = z12 * z[3];
            q[g][1] = z01;
            q[g][2] = z01 * z[2];
            q[g][3] = q[g][2] * z[3];
        }
        float hn[4];
        #pragma unroll
        for (int w = 0; w < 4; w++) {
            float fv = sigmoidf_fast(q[0][w]);
            float iv = sigmoidf_fast(q[1][w]);
            float gv = tanhf_fast(q[2][w]);
            float ov = sigmoidf_fast(q[3][w]);
            float c  = fmaf(fv, cx[w], iv * gv);
            cx[w] = c;
            hn[w] = ov * tanhf_fast(c);
        }
        hx[0] = hn[0]; hx[1] = hn[1]; hx[2] = hn[2]; hx[3] = hn[3];
        hout[s] = make_float4(hn[0], hn[1], hn[2], hn[3]);
    }
}

// ---------------------------------------------------------------------------
// Kernel C: logits [4 -> 10] + log_softmax. One thread per (b,s).
// ---------------------------------------------------------------------------
__global__ void out_kernel(const float* __restrict__ Wt, const float* __restrict__ bt,
                           float* __restrict__ out)
{
    int row = blockIdx.x * blockDim.x + threadIdx.x;
    if (row >= ROWS) return;
    float4 h = ((const float4*)g_h)[row];

    float lg[TT];
    #pragma unroll
    for (int t = 0; t < TT; t++) {
        float v = bt[t];
        v = fmaf(h.x, Wt[0 * TT + t], v);
        v = fmaf(h.y, Wt[1 * TT + t], v);
        v = fmaf(h.z, Wt[2 * TT + t], v);
        v = fmaf(h.w, Wt[3 * TT + t], v);
        lg[t] = v;
    }
    float m = lg[0];
    #pragma unroll
    for (int t = 1; t < TT; t++) m = fmaxf(m, lg[t]);
    float sum = 0.f;
    #pragma unroll
    for (int t = 0; t < TT; t++) sum += __expf(lg[t] - m);
    float lse = m + __logf(sum);
    #pragma unroll
    for (int t = 0; t < TT; t++) out[row * TT + t] = lg[t] - lse;
}

// ---------------------------------------------------------------------------
extern "C" void kernel_launch(void* const* d_in, const int* in_sizes, int n_in,
                              void* d_out, int out_size)
{
    (void)in_sizes; (void)n_in; (void)out_size;
    const int*   x   = (const int*)  d_in[0];
    const float* emb = (const float*)d_in[1];
    const float* Wf  = (const float*)d_in[2];
    const float* bf  = (const float*)d_in[3];
    const float* thf = (const float*)d_in[4];
    const float* Wi  = (const float*)d_in[5];
    const float* bi  = (const float*)d_in[6];
    const float* thi = (const float*)d_in[7];
    const float* Wu  = (const float*)d_in[8];
    const float* bu  = (const float*)d_in[9];
    const float* thu = (const float*)d_in[10];
    const float* Wo  = (const float*)d_in[11];
    const float* bo  = (const float*)d_in[12];
    const float* tho = (const float*)d_in[13];
    const float* Wt  = (const float*)d_in[14];
    const float* bt  = (const float*)d_in[15];
    float* out = (float*)d_out;

    pre_kernel<<<(ROWS * 16) / 256, 256>>>(x, emb, Wf, bf, thf, Wi, bi, thi,
                                           Wu, bu, thu, Wo, bo, tho);
    rec_kernel<<<2, 32>>>(Wf, Wi, Wu, Wo);
    out_kernel<<<ROWS / 256, 256>>>(Wt, bt, out);
}

// round 2
// speedup vs baseline: 1.7367x; 1.7367x over previous
#include <cuda_runtime.h>

#define BB 64
#define SS 512
#define EE 128
#define TT 10
#define VV 100000
#define ROWS (BB*SS)

// scratch (static device globals: allocation-free)
__device__ float g_proj[VV * 16];   // vocab projection: [v][w*4+g]
__device__ float g_pre[ROWS * 16];  // per-row x-part preactivation + bias + theta, [row][w*4+g]
__device__ float g_h[ROWS * 4];     // hidden states per (b,s), [row][w]

// ---------------------------------------------------------------------------
// Kernel A1: project the ENTIRE vocab through the 4 gate weight matrices.
// proj[v][w*4+g] = sum_k emb[v][k] * Wg[k*4+w].  Streaming 51MB read (fast)
// instead of a 14MB random gather (slow).
// ---------------------------------------------------------------------------
__global__ void proj_kernel(const float* __restrict__ emb,
                            const float* __restrict__ Wf, const float* __restrict__ Wi,
                            const float* __restrict__ Wu, const float* __restrict__ Wo)
{
    __shared__ float sW[128 * 16];  // sW[k*16 + w*4 + g] = Wg[k*4+w]
    int tid = threadIdx.x;
    for (int idx = tid; idx < 128 * 16; idx += blockDim.x) {
        int k = idx >> 4;
        int w = (idx >> 2) & 3;
        int g = idx & 3;
        const float* Wg = (g == 0) ? Wf : (g == 1) ? Wi : (g == 2) ? Wu : Wo;
        sW[idx] = Wg[k * 4 + w];
    }
    __syncthreads();

    int t = blockIdx.x * blockDim.x + tid;   // [0, VV*16)
    int j = t & 15;
    int v = t >> 4;
    const float4* e4 = (const float4*)(emb + (size_t)v * EE);

    float a0 = 0.f, a1 = 0.f, a2 = 0.f, a3 = 0.f;
    #pragma unroll
    for (int k4 = 0; k4 < 32; k4++) {
        float4 e = e4[k4];
        int k = k4 * 4;
        a0 = fmaf(e.x, sW[(k + 0) * 16 + j], a0);
        a1 = fmaf(e.y, sW[(k + 1) * 16 + j], a1);
        a2 = fmaf(e.z, sW[(k + 2) * 16 + j], a2);
        a3 = fmaf(e.w, sW[(k + 3) * 16 + j], a3);
    }
    g_proj[t] = (a0 + a1) + (a2 + a3);
}

// ---------------------------------------------------------------------------
// Kernel A2: gather 64B per row from the (L2-resident) projection table and
// add bias + theta.
// ---------------------------------------------------------------------------
__global__ void gather_kernel(const int* __restrict__ x,
                              const float* __restrict__ bf, const float* __restrict__ thf,
                              const float* __restrict__ bi, const float* __restrict__ thi,
                              const float* __restrict__ bu, const float* __restrict__ thu,
                              const float* __restrict__ bo, const float* __restrict__ tho)
{
    __shared__ float sC[16];  // sC[w*4+g] = b_g[w] + th_g[w]
    int tid = threadIdx.x;
    if (tid < 16) {
        int w = tid >> 2, g = tid & 3;
        const float* bg  = (g == 0) ? bf  : (g == 1) ? bi  : (g == 2) ? bu  : bo;
        const float* thg = (g == 0) ? thf : (g == 1) ? thi : (g == 2) ? thu : tho;
        sC[tid] = bg[w] + thg[w];
    }
    __syncthreads();

    int rid = blockIdx.x * blockDim.x + tid;
    if (rid >= ROWS) return;
    int token = x[rid];
    const float4* src = (const float4*)g_proj + (size_t)token * 4;
    float4* dst = (float4*)g_pre + (size_t)rid * 4;
    #pragma unroll
    for (int q = 0; q < 4; q++) {
        float4 v = src[q];
        v.x += sC[q * 4 + 0];
        v.y += sC[q * 4 + 1];
        v.z += sC[q * 4 + 2];
        v.w += sC[q * 4 + 3];
        dst[q] = v;
    }
}

// ---------------------------------------------------------------------------
// Kernel B: serial LSTM recurrence, wire-parallel: 4 lanes per batch element.
// Lane w computes gate angles a[g] for its wire, z=cos, then gathers z across
// wires via shfl to form the QLayer products:
//   out_w: w=0 -> z1 z2 z3 ; w=1 -> z0 z1 ; w=2 -> z0 z1 z2 ; w=3 -> z0 z1 z2 z3
// Gate math with fused reciprocals:
//   c = (cx*B*G + (2-G)*A) / (A*B*G),  A=1+e^{-qf}, B=1+e^{-qi}, G=1+e^{-2qu}
//   h = (1-e^{-2c}) / ((1+e^{-qo})(1+e^{-2c}))
// ---------------------------------------------------------------------------
__global__ void __launch_bounds__(32, 1) rec_kernel(const float* __restrict__ Wf,
                                                    const float* __restrict__ Wi,
                                                    const float* __restrict__ Wu,
                                                    const float* __restrict__ Wo)
{
    const unsigned FULL = 0xffffffffu;
    int lane = threadIdx.x;
    int w = lane & 3;
    int b = blockIdx.x * 8 + (lane >> 2);

    // hidden-to-gate weights for this wire: Wh[g][h] = Wg[(128+h)*4 + w]
    const float* Ws[4] = {Wf, Wi, Wu, Wo};
    float Wh[4][4];
    #pragma unroll
    for (int g = 0; g < 4; g++)
        #pragma unroll
        for (int h = 0; h < 4; h++)
            Wh[g][h] = Ws[g][(128 + h) * 4 + w];

    // product masks for this wire's QLayer output
    const bool m0 = (w != 0);
    const bool m1 = true;
    const bool m2 = (w == 0) | (w >= 2);
    const bool m3 = (w == 0) | (w == 3);

    const float4* pp = (const float4*)g_pre + (size_t)b * 2048 + w;  // [s*4]
    float* hout = g_h + (size_t)b * 2048 + w;                         // [s*4]

    float hv = 0.f, cx = 0.f;

    // software prefetch, distance 2
    float4 pb0 = pp[0];
    float4 pb1 = pp[4];

    for (int s = 0; s < SS; s++) {
        float4 p4 = pb0;
        pb0 = pb1;
        if (s + 2 < SS) pb1 = pp[4 * (s + 2)];

        // broadcast hidden state across the 4-lane group
        float hx0 = __shfl_sync(FULL, hv, 0, 4);
        float hx1 = __shfl_sync(FULL, hv, 1, 4);
        float hx2 = __shfl_sync(FULL, hv, 2, 4);
        float hx3 = __shfl_sync(FULL, hv, 3, 4);

        // angles for all 4 gates at this wire (balanced fma trees)
        float a0 = fmaf(hx1, Wh[0][1], fmaf(hx0, Wh[0][0], p4.x)) + fmaf(hx3, Wh[0][3], hx2 * Wh[0][2]);
        float a1 = fmaf(hx1, Wh[1][1], fmaf(hx0, Wh[1][0], p4.y)) + fmaf(hx3, Wh[1][3], hx2 * Wh[1][2]);
        float a2 = fmaf(hx1, Wh[2][1], fmaf(hx0, Wh[2][0], p4.z)) + fmaf(hx3, Wh[2][3], hx2 * Wh[2][2]);
        float a3 = fmaf(hx1, Wh[3][1], fmaf(hx0, Wh[3][0], p4.w)) + fmaf(hx3, Wh[3][3], hx2 * Wh[3][2]);

        float z0 = __cosf(a0);
        float z1 = __cosf(a1);
        float z2 = __cosf(a2);
        float z3 = __cosf(a3);

        // gather z across wires per gate and form masked products
        float q[4];
        {
            float zs[4] = {z0, z1, z2, z3};
            #pragma unroll
            for (int g = 0; g < 4; g++) {
                float v0 = __shfl_sync(FULL, zs[g], 0, 4);
                float v1 = __shfl_sync(FULL, zs[g], 1, 4);
                float v2 = __shfl_sync(FULL, zs[g], 2, 4);
                float v3 = __shfl_sync(FULL, zs[g], 3, 4);
                float t0 = m0 ? v0 : 1.0f;
                float t1 = m1 ? v1 : 1.0f;
                float t2 = m2 ? v2 : 1.0f;
                float t3 = m3 ? v3 : 1.0f;
                q[g] = (t0 * t1) * (t2 * t3);
            }
        }

        // gates with fused reciprocals
        float ef = __expf(-q[0]);
        float ei = __expf(-q[1]);
        float eg = __expf(-2.0f * q[2]);
        float eo = __expf(-q[3]);

        float A = 1.0f + ef;
        float B = 1.0f + ei;
        float G = 1.0f + eg;
        float P = B * G;
        float D = A * P;
        float num = fmaf(cx, P, (2.0f - G) * A);
        float c = __fdividef(num, D);

        float ec = __expf(-2.0f * c);
        float hn = __fdividef(1.0f - ec, (1.0f + eo) * (1.0f + ec));

        cx = c;
        hv = hn;
        hout[4 * s] = hn;
    }
}

// ---------------------------------------------------------------------------
// Kernel C: logits [4 -> 10] + log_softmax. One thread per (b,s).
// ---------------------------------------------------------------------------
__global__ void out_kernel(const float* __restrict__ Wt, const float* __restrict__ bt,
                           float* __restrict__ out)
{
    int row = blockIdx.x * blockDim.x + threadIdx.x;
    if (row >= ROWS) return;
    float4 h = ((const float4*)g_h)[row];

    float lg[TT];
    #pragma unroll
    for (int t = 0; t < TT; t++) {
        float v = bt[t];
        v = fmaf(h.x, Wt[0 * TT + t], v);
        v = fmaf(h.y, Wt[1 * TT + t], v);
        v = fmaf(h.z, Wt[2 * TT + t], v);
        v = fmaf(h.w, Wt[3 * TT + t], v);
        lg[t] = v;
    }
    float m = lg[0];
    #pragma unroll
    for (int t = 1; t < TT; t++) m = fmaxf(m, lg[t]);
    float sum = 0.f;
    #pragma unroll
    for (int t = 0; t < TT; t++) sum += __expf(lg[t] - m);
    float lse = m + __logf(sum);
    #pragma unroll
    for (int t = 0; t < TT; t++) out[row * TT + t] = lg[t] - lse;
}

// ---------------------------------------------------------------------------
extern "C" void kernel_launch(void* const* d_in, const int* in_sizes, int n_in,
                              void* d_out, int out_size)
{
    (void)in_sizes; (void)n_in; (void)out_size;
    const int*   x   = (const int*)  d_in[0];
    const float* emb = (const float*)d_in[1];
    const float* Wf  = (const float*)d_in[2];
    const float* bf  = (const float*)d_in[3];
    const float* thf = (const float*)d_in[4];
    const float* Wi  = (const float*)d_in[5];
    const float* bi  = (const float*)d_in[6];
    const float* thi = (const float*)d_in[7];
    const float* Wu  = (const float*)d_in[8];
    const float* bu  = (const float*)d_in[9];
    const float* thu = (const float*)d_in[10];
    const float* Wo  = (const float*)d_in[11];
    const float* bo  = (const float*)d_in[12];
    const float* tho = (const float*)d_in[13];
    const float* Wt  = (const float*)d_in[14];
    const float* bt  = (const float*)d_in[15];
    float* out = (float*)d_out;

    proj_kernel<<<(VV * 16) / 256, 256>>>(emb, Wf, Wi, Wu, Wo);
    gather_kernel<<<ROWS / 256, 256>>>(x, bf, thf, bi, thi, bu, thu, bo, tho);
    rec_kernel<<<8, 32>>>(Wf, Wi, Wu, Wo);
    out_kernel<<<ROWS / 256, 256>>>(Wt, bt, out);
}